// round 13
// baseline (speedup 1.0000x reference)
#include <cuda_runtime.h>

#define BATCH 64
#define CIN   96
#define CHID  256
#define COUT  80
#define TLEN  2048
#define NSM   148

// ---- scratch (allocation-free rule: __device__ globals) ----
static __device__ float    g_z1[(size_t)BATCH * TLEN * CHID];          // 128 MiB  [b][t][o]
static __device__ float    g_z2[(size_t)BATCH * TLEN * COUT];          // 40 MiB   [b][j][t]
static __device__ unsigned g_xbits[(size_t)BATCH * TLEN * 4];          // 2 MiB
static __device__ unsigned g_s1bits[(size_t)BATCH * TLEN * (CHID/32)]; // 4 MiB
static __device__ int      g_prog[BATCH];                              // scan progress (superblocks)
static __device__ int      g_widx;                                     // work-steal counter

// =====================================================================
// K0: build 96-bit input-activity masks per (b,t) + zero sync state.
// =====================================================================
__global__ __launch_bounds__(256) void k0_xbits(const float* __restrict__ x) {
    const int gid = blockIdx.x * 256 + threadIdx.x;   // 0 .. 64*2048-1
    if (gid < BATCH) g_prog[gid] = 0;
    if (gid == BATCH) g_widx = 0;
    const int b = gid >> 11;
    const int t = gid & 2047;
    const float* xp = x + (size_t)b * CIN * TLEN + t;
    unsigned m0 = 0, m1 = 0, m2 = 0;
    #pragma unroll
    for (int i = 0; i < 32; i++) if (__ldg(xp + (size_t)i * TLEN) != 0.0f)        m0 |= 1u << i;
    #pragma unroll
    for (int i = 0; i < 32; i++) if (__ldg(xp + (size_t)(i + 32) * TLEN) != 0.0f) m1 |= 1u << i;
    #pragma unroll
    for (int i = 0; i < 32; i++) if (__ldg(xp + (size_t)(i + 64) * TLEN) != 0.0f) m2 |= 1u << i;
    *(uint4*)&g_xbits[(size_t)gid * 4] = make_uint4(m0, m1, m2, 0u);
}

// =====================================================================
// K1: layer-1 sparse GEMM, PERSISTENT + o-split. (round-11, unchanged)
// =====================================================================
#define K1_T 128
#define W1ST 528                      // bytes per w1t row (132 floats)
__global__ __launch_bounds__(1024, 2) void k1_gemm1(const float* __restrict__ W1) {
    extern __shared__ char sm[];
    float*          w1t    = (float*)sm;                    // [97][132] = 51216 B
    unsigned short* lists  = (unsigned short*)(sm + 51216); // [128][104] = 26624 B
    int*            counts = (int*)(sm + 77840);            // [128]

    const int tid  = threadIdx.x;
    const int half = (blockIdx.x >= NSM) ? 1 : 0;
    const int slot = blockIdx.x - half * NSM;               // 0..147
    const int o0   = half * 128;

    for (int idx = tid; idx < 128 * CIN; idx += 1024) {
        int ol = idx / CIN, i = idx % CIN;
        w1t[i * 132 + ol] = W1[(size_t)(o0 + ol) * CIN + i];
    }
    for (int idx = tid; idx < 132; idx += 1024) w1t[96 * 132 + idx] = 0.0f;

    const int grp  = tid >> 5;
    const int lane = tid & 31;
    const char* wb = (const char*)w1t + lane * 16;

    const int nwork = (TLEN / K1_T) * BATCH;                // 1024 per half
    for (int w = slot; w < nwork; w += NSM) {
        const int tc = w & 15;
        const int b  = w >> 4;
        const int t0 = tc * K1_T;

        __syncthreads();
        if (tid < K1_T) {
            uint4 mw = *(const uint4*)&g_xbits[((size_t)b * TLEN + t0 + tid) * 4];
            unsigned short* L = lists + tid * 104;
            int c = 0;
            unsigned m = mw.x;
            while (m) { int k = __ffs(m) - 1; m &= m - 1; L[c++] = (unsigned short)(k * W1ST); }
            m = mw.y;
            while (m) { int k = __ffs(m) - 1; m &= m - 1; L[c++] = (unsigned short)((k + 32) * W1ST); }
            m = mw.z;
            while (m) { int k = __ffs(m) - 1; m &= m - 1; L[c++] = (unsigned short)((k + 64) * W1ST); }
            while (c & 3) L[c++] = (unsigned short)(96 * W1ST);
            counts[tid] = c;
        }
        __syncthreads();

        float* zp = g_z1 + ((size_t)b * TLEN + t0) * CHID + o0 + lane * 4;
        for (int tt = grp; tt < K1_T; tt += 32) {
            const unsigned short* L = lists + tt * 104;
            const int cnt = counts[tt];
            float a0 = 0.0f, a1 = 0.0f, a2 = 0.0f, a3 = 0.0f;
            for (int p = 0; p < cnt; p += 4) {
                uint2 e = *(const uint2*)(L + p);
                float4 w0 = *(const float4*)(wb + (e.x & 0xffff));
                float4 w1 = *(const float4*)(wb + (e.x >> 16));
                float4 w2 = *(const float4*)(wb + (e.y & 0xffff));
                float4 w3 = *(const float4*)(wb + (e.y >> 16));
                a0 += w0.x; a1 += w0.y; a2 += w0.z; a3 += w0.w;
                a0 += w1.x; a1 += w1.y; a2 += w1.z; a3 += w1.w;
                a0 += w2.x; a1 += w2.y; a2 += w2.z; a3 += w2.w;
                a0 += w3.x; a1 += w3.y; a2 += w3.z; a3 += w3.w;
            }
            *(float4*)(zp + (size_t)tt * CHID) = make_float4(a0, a1, a2, a3);
        }
    }
}

// =====================================================================
// K23: FUSED layer-1 LIF scan + layer-2 sparse GEMM with role-split
// CTAs and window-granular flag sync.
//   scan-role: bids < 148 with bid%7==0 (22 CTAs — ALL placed in wave 1
//   even at 1 CTA/SM -> deadlock-free). Each owns 3 batches; z1 staged
//   through a smem tile per 32-step superblock (low regs); emits spikes,
//   ballot-packed bits, then release-publishes g_prog[b] = sb+1.
//   gemm-role: 298 CTAs, round-11 k3 body; chunks claimed via atomic
//   g_widx in tc-major order; acquire-spin on g_prog[b] >= tc+1.
// LIF math: v = fma(v,0.95,z); ascending-o sums; bit-exact.
// =====================================================================
#define K3_T 32
__global__ __launch_bounds__(768, 2) void k23_fused(const float* __restrict__ W2,
                                                    float* __restrict__ out) {
    extern __shared__ char sm[];
    const int tid = threadIdx.x;
    const int bid = blockIdx.x;
    const bool scan_role = (bid < NSM) && (bid % 7 == 0);   // 22 CTAs

    if (scan_role) {
        float* tile = (float*)sm;               // [3][32][256] = 98304 B
        const int c  = bid / 7;                 // 0..21
        const int b0 = 3 * c;                   // batches b0..b0+2
        const int o = tid & 255, bslot = tid >> 8, lane = tid & 31;
        const int b = b0 + bslot;
        const bool act = (b < BATCH);
        float v = 0.0f;
        unsigned keep = 0;
        float*    so = out + ((size_t)(act ? b : 0) * CHID + o) * TLEN;
        unsigned* bw = g_s1bits + (size_t)(act ? b : 0) * TLEN * 8 + (o >> 5);

        for (int sb = 0; sb < 64; sb++) {
            __syncthreads();                    // tile reuse safe
            // cooperative tile load: 6144 float4, fully coalesced
            for (int idx = tid; idx < 6144; idx += 768) {
                int o4 = idx & 63, tt2 = (idx >> 6) & 31, bs = idx >> 11;
                int bb = b0 + bs;
                if (bb < BATCH)
                    *(float4*)(tile + (bs * 32 + tt2) * 256 + o4 * 4) =
                        __ldg((const float4*)(g_z1 + ((size_t)bb * TLEN + sb * 32 + tt2) * CHID) + o4);
            }
            __syncthreads();
            if (act) {
                const float* zc = tile + bslot * 8192 + o;
                const int tb = sb * 32;
                #pragma unroll
                for (int u4 = 0; u4 < 32; u4 += 4) {
                    float sv[4];
                    #pragma unroll
                    for (int u = 0; u < 4; u++) {
                        const int st = u4 + u;
                        v = __fmaf_rn(v, 0.95f, zc[st * 256]);
                        bool sp = (v >= 1.0f);
                        sv[u] = sp ? 1.0f : 0.0f;
                        unsigned bal = __ballot_sync(0xffffffffu, sp);
                        keep = (lane == st) ? bal : keep;
                        v = sp ? 0.0f : v;
                    }
                    *(float4*)(so + tb + u4) = make_float4(sv[0], sv[1], sv[2], sv[3]);
                }
                bw[(size_t)(tb + lane) * 8] = keep;   // one word per 32 steps
            }
            __threadfence();                    // release: bits visible at gpu scope
            __syncthreads();                    // all threads' fences done
            if (tid < 3 && b0 + tid < BATCH)
                atomicExch(&g_prog[b0 + tid], sb + 1);
        }
    } else {
        // ---- gemm-role: round-11 k3 body + work stealing ----
        float*          w2t    = (float*)sm;                    // [80][257] = 82240 B
        unsigned short* lists  = (unsigned short*)(sm + 82240); // [32][264] = 16896 B
        int*            counts = (int*)(sm + 99136);            // [32]
        float*          ztile  = (float*)(sm + 99264);          // [32][81] = 10368 B
        int*            wslot  = (int*)(sm + 109632);

        for (int idx = tid; idx < COUT * CHID; idx += 768) {
            int j = idx >> 8, o = idx & 255;
            w2t[j * 257 + o] = W2[idx];
        }
        for (int idx = tid; idx < COUT; idx += 768) w2t[idx * 257 + 256] = 0.0f;

        const int grp = tid / 96;            // 0..7 (3 full warps each)
        const int r   = tid % 96;

        for (;;) {
            __syncthreads();                 // previous iteration fully done
            if (tid == 0) {
                int w = atomicAdd(&g_widx, 1);
                if (w < 4096) {
                    int b = w & 63, tc = w >> 6;    // tc-major claim order
                    while (*((volatile int*)&g_prog[b]) < tc + 1) __nanosleep(128);
                    __threadfence();               // acquire
                }
                *wslot = w;
            }
            __syncthreads();
            const int w = *wslot;
            if (w >= 4096) break;
            const int b  = w & 63;
            const int t0 = (w >> 6) * K3_T;

            if (tid < K3_T) {  // ascending-o list, entries = 4*o (byte offset)
                const unsigned* sb = g_s1bits + ((size_t)b * TLEN + t0 + tid) * 8;
                unsigned short* L = lists + tid * 264;
                int c = 0;
                #pragma unroll
                for (int ww = 0; ww < 8; ww++) {
                    unsigned m = sb[ww];
                    while (m) {
                        int k = __ffs(m) - 1;
                        m &= m - 1;
                        L[c++] = (unsigned short)(((ww << 5) + k) << 2);
                    }
                }
                while (c & 3) L[c++] = (unsigned short)(256 << 2);
                counts[tid] = c;
            }
            __syncthreads();

            if (r < COUT) {
                const char* wbp = (const char*)(w2t + r * 257);
                for (int q = grp; q < K3_T / 2; q += 8) {
                    const int tt = 2 * q;
                    const unsigned short* L0 = lists + tt * 264;
                    const unsigned short* L1 = L0 + 264;
                    const int c0 = counts[tt], c1 = counts[tt + 1];
                    const int cmin = c0 < c1 ? c0 : c1;
                    float a0 = 0.0f, a1 = 0.0f;
                    int p = 0;
                    for (; p < cmin; p += 4) {   // two interleaved chains
                        uint2 e0 = *(const uint2*)(L0 + p);
                        uint2 e1 = *(const uint2*)(L1 + p);
                        a0 += *(const float*)(wbp + (e0.x & 0xffff));
                        a1 += *(const float*)(wbp + (e1.x & 0xffff));
                        a0 += *(const float*)(wbp + (e0.x >> 16));
                        a1 += *(const float*)(wbp + (e1.x >> 16));
                        a0 += *(const float*)(wbp + (e0.y & 0xffff));
                        a1 += *(const float*)(wbp + (e1.y & 0xffff));
                        a0 += *(const float*)(wbp + (e0.y >> 16));
                        a1 += *(const float*)(wbp + (e1.y >> 16));
                    }
                    for (; p < c0; p += 4) {
                        uint2 e0 = *(const uint2*)(L0 + p);
                        a0 += *(const float*)(wbp + (e0.x & 0xffff));
                        a0 += *(const float*)(wbp + (e0.x >> 16));
                        a0 += *(const float*)(wbp + (e0.y & 0xffff));
                        a0 += *(const float*)(wbp + (e0.y >> 16));
                    }
                    for (; p < c1; p += 4) {
                        uint2 e1 = *(const uint2*)(L1 + p);
                        a1 += *(const float*)(wbp + (e1.x & 0xffff));
                        a1 += *(const float*)(wbp + (e1.x >> 16));
                        a1 += *(const float*)(wbp + (e1.y & 0xffff));
                        a1 += *(const float*)(wbp + (e1.y >> 16));
                    }
                    ztile[tt * 81 + r]       = a0;
                    ztile[(tt + 1) * 81 + r] = a1;
                }
            }
            __syncthreads();

            // transposed store-out: g_z2[b][j][t0..], float4, coalesced
            float* zo = g_z2 + (size_t)b * COUT * TLEN + t0;
            for (int idx = tid; idx < COUT * (K3_T / 4); idx += 768) {
                int j = idx >> 3, q = idx & 7;
                float4 vv = make_float4(ztile[(4 * q + 0) * 81 + j],
                                        ztile[(4 * q + 1) * 81 + j],
                                        ztile[(4 * q + 2) * 81 + j],
                                        ztile[(4 * q + 3) * 81 + j]);
                *(float4*)(zo + (size_t)j * TLEN + 4 * q) = vv;
            }
        }
    }
}

// =====================================================================
// K4: layer-2 LIF scan. 80 CTAs x 64 thr. Contiguous float4 loads.
// =====================================================================
__device__ __forceinline__ void proc32(float& v, const float (&z)[32],
                                       int tbase, float* __restrict__ so) {
    #pragma unroll
    for (int u8 = 0; u8 < 32; u8 += 8) {
        float sv[8];
        #pragma unroll
        for (int u = 0; u < 8; u++) {
            v = __fmaf_rn(v, 0.95f, z[u8 + u]);
            bool sp = (v >= 1.0f);
            sv[u] = sp ? 1.0f : 0.0f;
            v = sp ? 0.0f : v;
        }
        *(float4*)(so + tbase + u8)     = make_float4(sv[0], sv[1], sv[2], sv[3]);
        *(float4*)(so + tbase + u8 + 4) = make_float4(sv[4], sv[5], sv[6], sv[7]);
    }
}

#define LD32C(dst, zp, t) { _Pragma("unroll") \
    for (int u = 0; u < 8; u++) *(float4*)((dst) + 4 * u) = \
        __ldg((const float4*)((zp) + (t)) + u); }

__global__ __launch_bounds__(64) void k4_scan2(float* __restrict__ out) {
    const int gid = blockIdx.x * 64 + threadIdx.x;   // 0..5119
    const int b = gid / COUT;
    const int j = gid % COUT;
    const float* z  = g_z2 + ((size_t)b * COUT + j) * TLEN;
    float*       so = out + (size_t)BATCH * CHID * TLEN
                          + ((size_t)b * COUT + j) * TLEN;

    float A[32], B[32], C[32], D[32];
    float v = 0.0f;
    LD32C(A, z, 0); LD32C(B, z, 32); LD32C(C, z, 64);

    for (int bi = 0; bi < 64; bi += 4) {
        const int t = bi * 32;
        if (bi + 3 < 64) LD32C(D, z, t + 96);
        proc32(v, A, t, so);
        if (bi + 4 < 64) LD32C(A, z, t + 128);
        proc32(v, B, t + 32, so);
        if (bi + 5 < 64) LD32C(B, z, t + 160);
        proc32(v, C, t + 64, so);
        if (bi + 6 < 64) LD32C(C, z, t + 192);
        proc32(v, D, t + 96, so);
    }
}

// =====================================================================
extern "C" void kernel_launch(void* const* d_in, const int* in_sizes, int n_in,
                              void* d_out, int out_size) {
    const float* x  = (const float*)d_in[0];   // [64, 96, 2048]
    const float* W1 = (const float*)d_in[1];   // [256, 96]
    const float* W2 = (const float*)d_in[2];   // [80, 256]
    float* out = (float*)d_out;                // spk1 ++ spk2

    const int smem1  = 77840 + 512;            // 78352  -> 2 CTAs/SM
    const int smem23 = 109632 + 16;            // 109648 -> 2 CTAs/SM
    cudaFuncSetAttribute(k1_gemm1,  cudaFuncAttributeMaxDynamicSharedMemorySize, smem1);
    cudaFuncSetAttribute(k23_fused, cudaFuncAttributeMaxDynamicSharedMemorySize, smem23);

    k0_xbits<<<(BATCH * TLEN) / 256, 256>>>(x);
    k1_gemm1<<<2 * NSM, 1024, smem1>>>(W1);
    k23_fused<<<320, 768, smem23>>>(W2, out);
    k4_scan2<<<(BATCH * COUT) / 64, 64>>>(out);
}

// round 15
// speedup vs baseline: 3.7861x; 3.7861x over previous
#include <cuda_runtime.h>

#define BATCH 64
#define CIN   96
#define CHID  256
#define COUT  80
#define TLEN  2048
#define NSM   148

// ---- scratch (allocation-free rule: __device__ globals) ----
static __device__ float    g_z1[(size_t)BATCH * TLEN * CHID];          // [b][t][o]
static __device__ float    g_z2[(size_t)BATCH * TLEN * COUT];          // [b][j][t]
static __device__ unsigned g_xbits[(size_t)BATCH * TLEN * 4];
static __device__ unsigned g_s1bits[(size_t)BATCH * TLEN * (CHID/32)];

// =====================================================================
// K0: build 96-bit input-activity masks per (b,t). Coalesced LDGs.
// =====================================================================
__global__ __launch_bounds__(256) void k0_xbits(const float* __restrict__ x) {
    const int gid = blockIdx.x * 256 + threadIdx.x;   // 0 .. 64*2048-1
    const int b = gid >> 11;
    const int t = gid & 2047;
    const float* xp = x + (size_t)b * CIN * TLEN + t;
    unsigned m0 = 0, m1 = 0, m2 = 0;
    #pragma unroll
    for (int i = 0; i < 32; i++) if (__ldg(xp + (size_t)i * TLEN) != 0.0f)        m0 |= 1u << i;
    #pragma unroll
    for (int i = 0; i < 32; i++) if (__ldg(xp + (size_t)(i + 32) * TLEN) != 0.0f) m1 |= 1u << i;
    #pragma unroll
    for (int i = 0; i < 32; i++) if (__ldg(xp + (size_t)(i + 64) * TLEN) != 0.0f) m2 |= 1u << i;
    *(uint4*)&g_xbits[(size_t)gid * 4] = make_uint4(m0, m1, m2, 0u);
}

// =====================================================================
// K1: layer-1 sparse GEMM, PERSISTENT + o-split. (round-11, unchanged)
// =====================================================================
#define K1_T 128
#define W1ST 528                      // bytes per w1t row (132 floats)
__global__ __launch_bounds__(1024, 2) void k1_gemm1(const float* __restrict__ W1) {
    extern __shared__ char sm[];
    float*          w1t    = (float*)sm;                    // [97][132] = 51216 B
    unsigned short* lists  = (unsigned short*)(sm + 51216); // [128][104] = 26624 B
    int*            counts = (int*)(sm + 77840);            // [128]

    const int tid  = threadIdx.x;
    const int half = (blockIdx.x >= NSM) ? 1 : 0;
    const int slot = blockIdx.x - half * NSM;               // 0..147
    const int o0   = half * 128;

    for (int idx = tid; idx < 128 * CIN; idx += 1024) {
        int ol = idx / CIN, i = idx % CIN;
        w1t[i * 132 + ol] = W1[(size_t)(o0 + ol) * CIN + i];
    }
    for (int idx = tid; idx < 132; idx += 1024) w1t[96 * 132 + idx] = 0.0f;

    const int grp  = tid >> 5;
    const int lane = tid & 31;
    const char* wb = (const char*)w1t + lane * 16;

    const int nwork = (TLEN / K1_T) * BATCH;                // 1024 per half
    for (int w = slot; w < nwork; w += NSM) {
        const int tc = w & 15;
        const int b  = w >> 4;
        const int t0 = tc * K1_T;

        __syncthreads();
        if (tid < K1_T) {
            uint4 mw = *(const uint4*)&g_xbits[((size_t)b * TLEN + t0 + tid) * 4];
            unsigned short* L = lists + tid * 104;
            int c = 0;
            unsigned m = mw.x;
            while (m) { int k = __ffs(m) - 1; m &= m - 1; L[c++] = (unsigned short)(k * W1ST); }
            m = mw.y;
            while (m) { int k = __ffs(m) - 1; m &= m - 1; L[c++] = (unsigned short)((k + 32) * W1ST); }
            m = mw.z;
            while (m) { int k = __ffs(m) - 1; m &= m - 1; L[c++] = (unsigned short)((k + 64) * W1ST); }
            while (c & 3) L[c++] = (unsigned short)(96 * W1ST);
            counts[tid] = c;
        }
        __syncthreads();

        float* zp = g_z1 + ((size_t)b * TLEN + t0) * CHID + o0 + lane * 4;
        for (int tt = grp; tt < K1_T; tt += 32) {
            const unsigned short* L = lists + tt * 104;
            const int cnt = counts[tt];
            float a0 = 0.0f, a1 = 0.0f, a2 = 0.0f, a3 = 0.0f;
            for (int p = 0; p < cnt; p += 4) {
                uint2 e = *(const uint2*)(L + p);
                float4 w0 = *(const float4*)(wb + (e.x & 0xffff));
                float4 w1 = *(const float4*)(wb + (e.x >> 16));
                float4 w2 = *(const float4*)(wb + (e.y & 0xffff));
                float4 w3 = *(const float4*)(wb + (e.y >> 16));
                a0 += w0.x; a1 += w0.y; a2 += w0.z; a3 += w0.w;
                a0 += w1.x; a1 += w1.y; a2 += w1.z; a3 += w1.w;
                a0 += w2.x; a1 += w2.y; a2 += w2.z; a3 += w2.w;
                a0 += w3.x; a1 += w3.y; a2 += w3.z; a3 += w3.w;
            }
            *(float4*)(zp + (size_t)tt * CHID) = make_float4(a0, a1, a2, a3);
        }
    }
}

// =====================================================================
// LIF step: SHORTENED critical chain.
//   v  = fma(v, 0.95f, z)          (4 cyc)
//   sv = set.ge.f32(v, 1.0f)       (ALU, 4 cyc — NOT a 13-cyc predicate)
//   v  = fma(-sv, v, v)            (4-5 cyc; sv=1 -> v-v=+0 exactly,
//                                   sv=0 -> v unchanged: bit-exact
//                                   vs reference v*(1-s))
// The ballot predicate (sv != 0) runs OFF the chain.
// =====================================================================
__device__ __forceinline__ float lif_step(float& v, float z) {
    v = __fmaf_rn(v, 0.95f, z);
    float sv;
    asm("set.ge.f32.f32 %0, %1, %2;" : "=f"(sv) : "f"(v), "f"(1.0f));
    v = __fmaf_rn(-sv, v, v);
    return sv;
}

__device__ __forceinline__ void proc32_bits(float& v, const float (&z)[32],
                                            int tbase, float* __restrict__ so,
                                            unsigned* __restrict__ bw, int lane) {
    unsigned keep = 0;
    #pragma unroll
    for (int u8 = 0; u8 < 32; u8 += 8) {
        float sv[8];
        #pragma unroll
        for (int u = 0; u < 8; u++) {
            const int st = u8 + u;
            sv[u] = lif_step(v, z[st]);
            unsigned bal = __ballot_sync(0xffffffffu, sv[u] != 0.0f);
            keep = (lane == st) ? bal : keep;
        }
        *(float4*)(so + tbase + u8)     = make_float4(sv[0], sv[1], sv[2], sv[3]);
        *(float4*)(so + tbase + u8 + 4) = make_float4(sv[4], sv[5], sv[6], sv[7]);
    }
    bw[(size_t)(tbase + lane) * (CHID/32)] = keep;
}

__device__ __forceinline__ void proc32(float& v, const float (&z)[32],
                                       int tbase, float* __restrict__ so) {
    #pragma unroll
    for (int u8 = 0; u8 < 32; u8 += 8) {
        float sv[8];
        #pragma unroll
        for (int u = 0; u < 8; u++) sv[u] = lif_step(v, z[u8 + u]);
        *(float4*)(so + tbase + u8)     = make_float4(sv[0], sv[1], sv[2], sv[3]);
        *(float4*)(so + tbase + u8 + 4) = make_float4(sv[4], sv[5], sv[6], sv[7]);
    }
}

// =====================================================================
// K2: layer-1 LIF scan. 128 CTAs x 128 thr = 16384 (one wave).
// 4 rotating 32-step register buffers (prefetch distance 3).
// =====================================================================
#define LD32(dst, zp, t) { _Pragma("unroll") \
    for (int u = 0; u < 32; u++) dst[u] = __ldg(zp + (size_t)((t) + u) * CHID); }

__global__ __launch_bounds__(128) void k2_scan1(float* __restrict__ out) {
    const int gid  = blockIdx.x * 128 + threadIdx.x;
    const int b    = gid >> 8;
    const int o    = gid & 255;
    const int lane = o & 31;
    const float* z  = g_z1 + (size_t)b * TLEN * CHID + o;
    float*       so = out + ((size_t)b * CHID + o) * TLEN;
    unsigned*    bw = g_s1bits + (size_t)b * TLEN * (CHID/32) + (o >> 5);

    float A[32], B[32], C[32], D[32];
    float v = 0.0f;
    LD32(A, z, 0); LD32(B, z, 32); LD32(C, z, 64);

    for (int bi = 0; bi < 64; bi += 4) {
        const int t = bi * 32;
        if (bi + 3 < 64) LD32(D, z, t + 96);
        proc32_bits(v, A, t, so, bw, lane);
        if (bi + 4 < 64) LD32(A, z, t + 128);
        proc32_bits(v, B, t + 32, so, bw, lane);
        if (bi + 5 < 64) LD32(B, z, t + 160);
        proc32_bits(v, C, t + 64, so, bw, lane);
        if (bi + 6 < 64) LD32(C, z, t + 192);
        proc32_bits(v, D, t + 96, so, bw, lane);
    }
}

// =====================================================================
// K3: layer-2 sparse GEMM, PERSISTENT. (round-11, unchanged)
// =====================================================================
#define K3_T 32
__global__ __launch_bounds__(768, 2) void k3_gemm2(const float* __restrict__ W2) {
    extern __shared__ char sm[];
    float*          w2t    = (float*)sm;                    // [80][257] = 82240 B
    unsigned short* lists  = (unsigned short*)(sm + 82240); // [32][264] = 16896 B
    int*            counts = (int*)(sm + 99136);            // [32]
    float*          ztile  = (float*)(sm + 99264);          // [32][81] = 10368 B

    const int tid = threadIdx.x;

    for (int idx = tid; idx < COUT * CHID; idx += 768) {
        int j = idx >> 8, o = idx & 255;
        w2t[j * 257 + o] = W2[idx];
    }
    for (int idx = tid; idx < COUT; idx += 768) w2t[idx * 257 + 256] = 0.0f;

    const int grp = tid / 96;            // 0..7 (3 full warps each)
    const int r   = tid % 96;

    const int nwork = (TLEN / K3_T) * BATCH;                // 4096
    for (int w = blockIdx.x; w < nwork; w += 2 * NSM) {
        const int tc = w & 63;
        const int b  = w >> 6;
        const int t0 = tc * K3_T;

        __syncthreads();
        if (tid < K3_T) {
            const unsigned* sb = g_s1bits + ((size_t)b * TLEN + t0 + tid) * 8;
            unsigned short* L = lists + tid * 264;
            int c = 0;
            #pragma unroll
            for (int ww = 0; ww < 8; ww++) {
                unsigned m = sb[ww];
                while (m) {
                    int k = __ffs(m) - 1;
                    m &= m - 1;
                    L[c++] = (unsigned short)(((ww << 5) + k) << 2);
                }
            }
            while (c & 3) L[c++] = (unsigned short)(256 << 2);
            counts[tid] = c;
        }
        __syncthreads();

        if (r < COUT) {
            const char* wbp = (const char*)(w2t + r * 257);
            for (int q = grp; q < K3_T / 2; q += 8) {
                const int tt = 2 * q;
                const unsigned short* L0 = lists + tt * 264;
                const unsigned short* L1 = L0 + 264;
                const int c0 = counts[tt], c1 = counts[tt + 1];
                const int cmin = c0 < c1 ? c0 : c1;
                float a0 = 0.0f, a1 = 0.0f;
                int p = 0;
                for (; p < cmin; p += 4) {   // two interleaved chains
                    uint2 e0 = *(const uint2*)(L0 + p);
                    uint2 e1 = *(const uint2*)(L1 + p);
                    a0 += *(const float*)(wbp + (e0.x & 0xffff));
                    a1 += *(const float*)(wbp + (e1.x & 0xffff));
                    a0 += *(const float*)(wbp + (e0.x >> 16));
                    a1 += *(const float*)(wbp + (e1.x >> 16));
                    a0 += *(const float*)(wbp + (e0.y & 0xffff));
                    a1 += *(const float*)(wbp + (e1.y & 0xffff));
                    a0 += *(const float*)(wbp + (e0.y >> 16));
                    a1 += *(const float*)(wbp + (e1.y >> 16));
                }
                for (; p < c0; p += 4) {
                    uint2 e0 = *(const uint2*)(L0 + p);
                    a0 += *(const float*)(wbp + (e0.x & 0xffff));
                    a0 += *(const float*)(wbp + (e0.x >> 16));
                    a0 += *(const float*)(wbp + (e0.y & 0xffff));
                    a0 += *(const float*)(wbp + (e0.y >> 16));
                }
                for (; p < c1; p += 4) {
                    uint2 e1 = *(const uint2*)(L1 + p);
                    a1 += *(const float*)(wbp + (e1.x & 0xffff));
                    a1 += *(const float*)(wbp + (e1.x >> 16));
                    a1 += *(const float*)(wbp + (e1.y & 0xffff));
                    a1 += *(const float*)(wbp + (e1.y >> 16));
                }
                ztile[tt * 81 + r]       = a0;
                ztile[(tt + 1) * 81 + r] = a1;
            }
        }
        __syncthreads();

        float* zo = g_z2 + (size_t)b * COUT * TLEN + t0;
        for (int idx = tid; idx < COUT * (K3_T / 4); idx += 768) {
            int j = idx >> 3, q = idx & 7;
            float4 vv = make_float4(ztile[(4 * q + 0) * 81 + j],
                                    ztile[(4 * q + 1) * 81 + j],
                                    ztile[(4 * q + 2) * 81 + j],
                                    ztile[(4 * q + 3) * 81 + j]);
            *(float4*)(zo + (size_t)j * TLEN + 4 * q) = vv;
        }
    }
}

// =====================================================================
// K4: layer-2 LIF scan. 80 CTAs x 64 thr. Contiguous float4 loads.
// =====================================================================
#define LD32C(dst, zp, t) { _Pragma("unroll") \
    for (int u = 0; u < 8; u++) *(float4*)((dst) + 4 * u) = \
        __ldg((const float4*)((zp) + (t)) + u); }

__global__ __launch_bounds__(64) void k4_scan2(float* __restrict__ out) {
    const int gid = blockIdx.x * 64 + threadIdx.x;   // 0..5119
    const int b = gid / COUT;
    const int j = gid % COUT;
    const float* z  = g_z2 + ((size_t)b * COUT + j) * TLEN;
    float*       so = out + (size_t)BATCH * CHID * TLEN
                          + ((size_t)b * COUT + j) * TLEN;

    float A[32], B[32], C[32], D[32];
    float v = 0.0f;
    LD32C(A, z, 0); LD32C(B, z, 32); LD32C(C, z, 64);

    for (int bi = 0; bi < 64; bi += 4) {
        const int t = bi * 32;
        if (bi + 3 < 64) LD32C(D, z, t + 96);
        proc32(v, A, t, so);
        if (bi + 4 < 64) LD32C(A, z, t + 128);
        proc32(v, B, t + 32, so);
        if (bi + 5 < 64) LD32C(B, z, t + 160);
        proc32(v, C, t + 64, so);
        if (bi + 6 < 64) LD32C(C, z, t + 192);
        proc32(v, D, t + 96, so);
    }
}

// =====================================================================
extern "C" void kernel_launch(void* const* d_in, const int* in_sizes, int n_in,
                              void* d_out, int out_size) {
    const float* x  = (const float*)d_in[0];   // [64, 96, 2048]
    const float* W1 = (const float*)d_in[1];   // [256, 96]
    const float* W2 = (const float*)d_in[2];   // [80, 256]
    float* out = (float*)d_out;                // spk1 ++ spk2

    const int smem1 = 77840 + 512;             // 78352  -> 2 CTAs/SM
    const int smem3 = 99264 + 10368;           // 109632 -> 2 CTAs/SM
    cudaFuncSetAttribute(k1_gemm1, cudaFuncAttributeMaxDynamicSharedMemorySize, smem1);
    cudaFuncSetAttribute(k3_gemm2, cudaFuncAttributeMaxDynamicSharedMemorySize, smem3);

    k0_xbits<<<(BATCH * TLEN) / 256, 256>>>(x);
    k1_gemm1<<<2 * NSM, 1024, smem1>>>(W1);
    k2_scan1<<<(BATCH * CHID) / 128, 128>>>(out);
    k3_gemm2<<<2 * NSM, 768, smem3>>>(W2);
    k4_scan2<<<(BATCH * COUT) / 64, 64>>>(out);
}

// round 16
// speedup vs baseline: 3.8428x; 1.0150x over previous
#include <cuda_runtime.h>

#define BATCH 64
#define CIN   96
#define CHID  256
#define COUT  80
#define TLEN  2048
#define NSM   148

// ---- scratch (allocation-free rule: __device__ globals) ----
static __device__ float    g_z1[(size_t)BATCH * TLEN * CHID];          // [b][t][o]
static __device__ float    g_z2[(size_t)BATCH * TLEN * COUT];          // [b][j][t]
static __device__ unsigned g_xbits[(size_t)BATCH * TLEN * 4];
static __device__ unsigned g_s1bits[(size_t)BATCH * TLEN * (CHID/32)];

// =====================================================================
// K0: build 96-bit input-activity masks per (b,t). Coalesced LDGs.
// =====================================================================
__global__ __launch_bounds__(256) void k0_xbits(const float* __restrict__ x) {
    const int gid = blockIdx.x * 256 + threadIdx.x;   // 0 .. 64*2048-1
    const int b = gid >> 11;
    const int t = gid & 2047;
    const float* xp = x + (size_t)b * CIN * TLEN + t;
    unsigned m0 = 0, m1 = 0, m2 = 0;
    #pragma unroll
    for (int i = 0; i < 32; i++) if (__ldg(xp + (size_t)i * TLEN) != 0.0f)        m0 |= 1u << i;
    #pragma unroll
    for (int i = 0; i < 32; i++) if (__ldg(xp + (size_t)(i + 32) * TLEN) != 0.0f) m1 |= 1u << i;
    #pragma unroll
    for (int i = 0; i < 32; i++) if (__ldg(xp + (size_t)(i + 64) * TLEN) != 0.0f) m2 |= 1u << i;
    *(uint4*)&g_xbits[(size_t)gid * 4] = make_uint4(m0, m1, m2, 0u);
}

// =====================================================================
// K1: layer-1 sparse GEMM, PERSISTENT + o-split. (round-11, unchanged)
// =====================================================================
#define K1_T 128
#define W1ST 528                      // bytes per w1t row (132 floats)
__global__ __launch_bounds__(1024, 2) void k1_gemm1(const float* __restrict__ W1) {
    extern __shared__ char sm[];
    float*          w1t    = (float*)sm;                    // [97][132] = 51216 B
    unsigned short* lists  = (unsigned short*)(sm + 51216); // [128][104] = 26624 B
    int*            counts = (int*)(sm + 77840);            // [128]

    const int tid  = threadIdx.x;
    const int half = (blockIdx.x >= NSM) ? 1 : 0;
    const int slot = blockIdx.x - half * NSM;               // 0..147
    const int o0   = half * 128;

    for (int idx = tid; idx < 128 * CIN; idx += 1024) {
        int ol = idx / CIN, i = idx % CIN;
        w1t[i * 132 + ol] = W1[(size_t)(o0 + ol) * CIN + i];
    }
    for (int idx = tid; idx < 132; idx += 1024) w1t[96 * 132 + idx] = 0.0f;

    const int grp  = tid >> 5;
    const int lane = tid & 31;
    const char* wb = (const char*)w1t + lane * 16;

    const int nwork = (TLEN / K1_T) * BATCH;                // 1024 per half
    for (int w = slot; w < nwork; w += NSM) {
        const int tc = w & 15;
        const int b  = w >> 4;
        const int t0 = tc * K1_T;

        __syncthreads();
        if (tid < K1_T) {
            uint4 mw = *(const uint4*)&g_xbits[((size_t)b * TLEN + t0 + tid) * 4];
            unsigned short* L = lists + tid * 104;
            int c = 0;
            unsigned m = mw.x;
            while (m) { int k = __ffs(m) - 1; m &= m - 1; L[c++] = (unsigned short)(k * W1ST); }
            m = mw.y;
            while (m) { int k = __ffs(m) - 1; m &= m - 1; L[c++] = (unsigned short)((k + 32) * W1ST); }
            m = mw.z;
            while (m) { int k = __ffs(m) - 1; m &= m - 1; L[c++] = (unsigned short)((k + 64) * W1ST); }
            while (c & 3) L[c++] = (unsigned short)(96 * W1ST);
            counts[tid] = c;
        }
        __syncthreads();

        float* zp = g_z1 + ((size_t)b * TLEN + t0) * CHID + o0 + lane * 4;
        for (int tt = grp; tt < K1_T; tt += 32) {
            const unsigned short* L = lists + tt * 104;
            const int cnt = counts[tt];
            float a0 = 0.0f, a1 = 0.0f, a2 = 0.0f, a3 = 0.0f;
            for (int p = 0; p < cnt; p += 4) {
                uint2 e = *(const uint2*)(L + p);
                float4 w0 = *(const float4*)(wb + (e.x & 0xffff));
                float4 w1 = *(const float4*)(wb + (e.x >> 16));
                float4 w2 = *(const float4*)(wb + (e.y & 0xffff));
                float4 w3 = *(const float4*)(wb + (e.y >> 16));
                a0 += w0.x; a1 += w0.y; a2 += w0.z; a3 += w0.w;
                a0 += w1.x; a1 += w1.y; a2 += w1.z; a3 += w1.w;
                a0 += w2.x; a1 += w2.y; a2 += w2.z; a3 += w2.w;
                a0 += w3.x; a1 += w3.y; a2 += w3.z; a3 += w3.w;
            }
            *(float4*)(zp + (size_t)tt * CHID) = make_float4(a0, a1, a2, a3);
        }
    }
}

// =====================================================================
// LIF step: shortened critical chain (set.ge ALU + reset-FMA), bit-exact
// vs reference (sv=1 -> v-v=+0; sv=0 -> v unchanged).
// =====================================================================
__device__ __forceinline__ float lif_step(float& v, float z) {
    v = __fmaf_rn(v, 0.95f, z);
    float sv;
    asm("set.ge.f32.f32 %0, %1, %2;" : "=f"(sv) : "f"(v), "f"(1.0f));
    v = __fmaf_rn(-sv, v, v);
    return sv;
}

__device__ __forceinline__ void proc32_bits(float& v, const float (&z)[32],
                                            int tbase, float* __restrict__ so,
                                            unsigned* __restrict__ bw, int lane) {
    unsigned keep = 0;
    #pragma unroll
    for (int u8 = 0; u8 < 32; u8 += 8) {
        float sv[8];
        #pragma unroll
        for (int u = 0; u < 8; u++) {
            const int st = u8 + u;
            sv[u] = lif_step(v, z[st]);
            unsigned bal = __ballot_sync(0xffffffffu, sv[u] != 0.0f);
            keep = (lane == st) ? bal : keep;
        }
        *(float4*)(so + tbase + u8)     = make_float4(sv[0], sv[1], sv[2], sv[3]);
        *(float4*)(so + tbase + u8 + 4) = make_float4(sv[4], sv[5], sv[6], sv[7]);
    }
    bw[(size_t)(tbase + lane) * (CHID/32)] = keep;
}

__device__ __forceinline__ void proc16(float& v, const float (&z)[16],
                                       int tbase, float* __restrict__ so) {
    #pragma unroll
    for (int u8 = 0; u8 < 16; u8 += 8) {
        float sv[8];
        #pragma unroll
        for (int u = 0; u < 8; u++) sv[u] = lif_step(v, z[u8 + u]);
        *(float4*)(so + tbase + u8)     = make_float4(sv[0], sv[1], sv[2], sv[3]);
        *(float4*)(so + tbase + u8 + 4) = make_float4(sv[4], sv[5], sv[6], sv[7]);
    }
}

// =====================================================================
// K2: layer-1 LIF scan. 128 CTAs x 128 thr = 16384 (one wave).
// 4 rotating 32-step register buffers (prefetch distance 3).
// =====================================================================
#define LD32(dst, zp, t) { _Pragma("unroll") \
    for (int u = 0; u < 32; u++) dst[u] = __ldg(zp + (size_t)((t) + u) * CHID); }

__global__ __launch_bounds__(128) void k2_scan1(float* __restrict__ out) {
    const int gid  = blockIdx.x * 128 + threadIdx.x;
    const int b    = gid >> 8;
    const int o    = gid & 255;
    const int lane = o & 31;
    const float* z  = g_z1 + (size_t)b * TLEN * CHID + o;
    float*       so = out + ((size_t)b * CHID + o) * TLEN;
    unsigned*    bw = g_s1bits + (size_t)b * TLEN * (CHID/32) + (o >> 5);

    float A[32], B[32], C[32], D[32];
    float v = 0.0f;
    LD32(A, z, 0); LD32(B, z, 32); LD32(C, z, 64);

    for (int bi = 0; bi < 64; bi += 4) {
        const int t = bi * 32;
        if (bi + 3 < 64) LD32(D, z, t + 96);
        proc32_bits(v, A, t, so, bw, lane);
        if (bi + 4 < 64) LD32(A, z, t + 128);
        proc32_bits(v, B, t + 32, so, bw, lane);
        if (bi + 5 < 64) LD32(B, z, t + 160);
        proc32_bits(v, C, t + 64, so, bw, lane);
        if (bi + 6 < 64) LD32(C, z, t + 192);
        proc32_bits(v, D, t + 96, so, bw, lane);
    }
}

// =====================================================================
// K3: layer-2 sparse GEMM, PERSISTENT. (round-11, unchanged)
// =====================================================================
#define K3_T 32
__global__ __launch_bounds__(768, 2) void k3_gemm2(const float* __restrict__ W2) {
    extern __shared__ char sm[];
    float*          w2t    = (float*)sm;                    // [80][257] = 82240 B
    unsigned short* lists  = (unsigned short*)(sm + 82240); // [32][264] = 16896 B
    int*            counts = (int*)(sm + 99136);            // [32]
    float*          ztile  = (float*)(sm + 99264);          // [32][81] = 10368 B

    const int tid = threadIdx.x;

    for (int idx = tid; idx < COUT * CHID; idx += 768) {
        int j = idx >> 8, o = idx & 255;
        w2t[j * 257 + o] = W2[idx];
    }
    for (int idx = tid; idx < COUT; idx += 768) w2t[idx * 257 + 256] = 0.0f;

    const int grp = tid / 96;            // 0..7 (3 full warps each)
    const int r   = tid % 96;

    const int nwork = (TLEN / K3_T) * BATCH;                // 4096
    for (int w = blockIdx.x; w < nwork; w += 2 * NSM) {
        const int tc = w & 63;
        const int b  = w >> 6;
        const int t0 = tc * K3_T;

        __syncthreads();
        if (tid < K3_T) {
            const unsigned* sb = g_s1bits + ((size_t)b * TLEN + t0 + tid) * 8;
            unsigned short* L = lists + tid * 264;
            int c = 0;
            #pragma unroll
            for (int ww = 0; ww < 8; ww++) {
                unsigned m = sb[ww];
                while (m) {
                    int k = __ffs(m) - 1;
                    m &= m - 1;
                    L[c++] = (unsigned short)(((ww << 5) + k) << 2);
                }
            }
            while (c & 3) L[c++] = (unsigned short)(256 << 2);
            counts[tid] = c;
        }
        __syncthreads();

        if (r < COUT) {
            const char* wbp = (const char*)(w2t + r * 257);
            for (int q = grp; q < K3_T / 2; q += 8) {
                const int tt = 2 * q;
                const unsigned short* L0 = lists + tt * 264;
                const unsigned short* L1 = L0 + 264;
                const int c0 = counts[tt], c1 = counts[tt + 1];
                const int cmin = c0 < c1 ? c0 : c1;
                float a0 = 0.0f, a1 = 0.0f;
                int p = 0;
                for (; p < cmin; p += 4) {   // two interleaved chains
                    uint2 e0 = *(const uint2*)(L0 + p);
                    uint2 e1 = *(const uint2*)(L1 + p);
                    a0 += *(const float*)(wbp + (e0.x & 0xffff));
                    a1 += *(const float*)(wbp + (e1.x & 0xffff));
                    a0 += *(const float*)(wbp + (e0.x >> 16));
                    a1 += *(const float*)(wbp + (e1.x >> 16));
                    a0 += *(const float*)(wbp + (e0.y & 0xffff));
                    a1 += *(const float*)(wbp + (e1.y & 0xffff));
                    a0 += *(const float*)(wbp + (e0.y >> 16));
                    a1 += *(const float*)(wbp + (e1.y >> 16));
                }
                for (; p < c0; p += 4) {
                    uint2 e0 = *(const uint2*)(L0 + p);
                    a0 += *(const float*)(wbp + (e0.x & 0xffff));
                    a0 += *(const float*)(wbp + (e0.x >> 16));
                    a0 += *(const float*)(wbp + (e0.y & 0xffff));
                    a0 += *(const float*)(wbp + (e0.y >> 16));
                }
                for (; p < c1; p += 4) {
                    uint2 e1 = *(const uint2*)(L1 + p);
                    a1 += *(const float*)(wbp + (e1.x & 0xffff));
                    a1 += *(const float*)(wbp + (e1.x >> 16));
                    a1 += *(const float*)(wbp + (e1.y & 0xffff));
                    a1 += *(const float*)(wbp + (e1.y >> 16));
                }
                ztile[tt * 81 + r]       = a0;
                ztile[(tt + 1) * 81 + r] = a1;
            }
        }
        __syncthreads();

        float* zo = g_z2 + (size_t)b * COUT * TLEN + t0;
        for (int idx = tid; idx < COUT * (K3_T / 4); idx += 768) {
            int j = idx >> 3, q = idx & 7;
            float4 vv = make_float4(ztile[(4 * q + 0) * 81 + j],
                                    ztile[(4 * q + 1) * 81 + j],
                                    ztile[(4 * q + 2) * 81 + j],
                                    ztile[(4 * q + 3) * 81 + j]);
            *(float4*)(zo + (size_t)j * TLEN + 4 * q) = vv;
        }
    }
}

// =====================================================================
// K4: layer-2 LIF scan. 160 CTAs x 32 thr (every SM busy).
// 4 rotating 16-step buffers (64 floats of buffer state -> NO register
// spill, vs 128 floats before), prefetch distance 3 (48 steps ~= 624cyc
// >= DRAM latency). Contiguous float4 loads from g_z2[b][j][t].
// =====================================================================
#define LD16C(dst, zp, t) { _Pragma("unroll") \
    for (int u = 0; u < 4; u++) *(float4*)((dst) + 4 * u) = \
        __ldg((const float4*)((zp) + (t)) + u); }

__global__ __launch_bounds__(32) void k4_scan2(float* __restrict__ out) {
    const int gid = blockIdx.x * 32 + threadIdx.x;   // 0..5119
    const int b = gid / COUT;
    const int j = gid % COUT;
    const float* z  = g_z2 + ((size_t)b * COUT + j) * TLEN;
    float*       so = out + (size_t)BATCH * CHID * TLEN
                          + ((size_t)b * COUT + j) * TLEN;

    float A[16], B[16], C[16], D[16];
    float v = 0.0f;
    LD16C(A, z, 0); LD16C(B, z, 16); LD16C(C, z, 32);

    for (int bi = 0; bi < 128; bi += 4) {
        const int t = bi * 16;
        if (bi + 3 < 128) LD16C(D, z, t + 48);
        proc16(v, A, t, so);
        if (bi + 4 < 128) LD16C(A, z, t + 64);
        proc16(v, B, t + 16, so);
        if (bi + 5 < 128) LD16C(B, z, t + 80);
        proc16(v, C, t + 32, so);
        if (bi + 6 < 128) LD16C(C, z, t + 96);
        proc16(v, D, t + 48, so);
    }
}

// =====================================================================
extern "C" void kernel_launch(void* const* d_in, const int* in_sizes, int n_in,
                              void* d_out, int out_size) {
    const float* x  = (const float*)d_in[0];   // [64, 96, 2048]
    const float* W1 = (const float*)d_in[1];   // [256, 96]
    const float* W2 = (const float*)d_in[2];   // [80, 256]
    float* out = (float*)d_out;                // spk1 ++ spk2

    const int smem1 = 77840 + 512;             // 78352  -> 2 CTAs/SM
    const int smem3 = 99264 + 10368;           // 109632 -> 2 CTAs/SM
    cudaFuncSetAttribute(k1_gemm1, cudaFuncAttributeMaxDynamicSharedMemorySize, smem1);
    cudaFuncSetAttribute(k3_gemm2, cudaFuncAttributeMaxDynamicSharedMemorySize, smem3);

    k0_xbits<<<(BATCH * TLEN) / 256, 256>>>(x);
    k1_gemm1<<<2 * NSM, 1024, smem1>>>(W1);
    k2_scan1<<<(BATCH * CHID) / 128, 128>>>(out);
    k3_gemm2<<<2 * NSM, 768, smem3>>>(W2);
    k4_scan2<<<(BATCH * COUT) / 32, 32>>>(out);
}